// round 1
// baseline (speedup 1.0000x reference)
#include <cuda_runtime.h>
#include <math.h>

// Problem constants
#define NB 4096   // batch
#define NP 4096   // W*H pixels
#define NF 1024   // filters

#define SHRINK 0.25f
#define LR 0.1f
#define B1 0.9f
#define B2 0.999f
#define EPS 1e-8f
#define WD 1e-2f
#define STEPS 50

// Persistent state (device globals; no allocation allowed)
__device__ float g_u[NB * NF];
__device__ float g_m[NB * NF];
__device__ float g_v[NB * NF];
__device__ float g_acta[NB * NF];
__device__ float g_actb[NB * NF];
__device__ float g_excite[NB * NF];
__device__ float g_G[NF * NF];

// GEMM tile config
constexpr int BM = 128, BN = 128, BK = 16, TM = 8, TN = 8, NTHR = 256;

// ---------------------------------------------------------------------------
// Generic tiled SGEMM: C[M,N] = op(A) * op(B)
//   TA=false: A row-major [M,K] (lda = row stride)
//   TA=true : A stored [K,M] (access A[k*lda + m])
//   TB=false: B row-major [K,N]
//   TB=true : B stored [N,K] (access B[n*ldb + k])
//   SUBI    : subtract identity from result (for G = PhiT*Phi - I)
// All of M, N multiples of 128; K multiple of 16 (true for this problem).
// ---------------------------------------------------------------------------
template <bool TA, bool TB, bool SUBI>
__global__ __launch_bounds__(NTHR) void gemm_kernel(
    const float* __restrict__ A, const float* __restrict__ B,
    float* __restrict__ C, int M, int N, int K, int lda, int ldb, int ldc)
{
    __shared__ float As[BK][BM + 4];
    __shared__ float Bs[BK][BN + 4];

    const int tid = threadIdx.x;
    const int m0 = blockIdx.y * BM;
    const int n0 = blockIdx.x * BN;
    const int tr = (tid >> 4) * TM;   // 0..120
    const int tc = (tid & 15) * TN;   // 0..120

    float acc[TM][TN];
#pragma unroll
    for (int i = 0; i < TM; i++)
#pragma unroll
        for (int j = 0; j < TN; j++) acc[i][j] = 0.0f;

    for (int k0 = 0; k0 < K; k0 += BK) {
        // Load A tile (BM x BK = 2048 elems, 8 per thread)
#pragma unroll
        for (int t = 0; t < (BM * BK) / NTHR; t++) {
            int idx = tid + t * NTHR;
            if (!TA) {
                int r = idx >> 4, c = idx & 15;
                As[c][r] = A[(size_t)(m0 + r) * lda + (k0 + c)];
            } else {
                int mm = idx & (BM - 1), kk = idx >> 7;
                As[kk][mm] = A[(size_t)(k0 + kk) * lda + (m0 + mm)];
            }
        }
        // Load B tile (BK x BN)
#pragma unroll
        for (int t = 0; t < (BN * BK) / NTHR; t++) {
            int idx = tid + t * NTHR;
            if (!TB) {
                int n = idx & (BN - 1), kk = idx >> 7;
                Bs[kk][n] = B[(size_t)(k0 + kk) * ldb + (n0 + n)];
            } else {
                int kk = idx & 15, n = idx >> 4;
                Bs[kk][n] = B[(size_t)(n0 + n) * ldb + (k0 + kk)];
            }
        }
        __syncthreads();

#pragma unroll
        for (int kk = 0; kk < BK; kk++) {
            float a[TM], b[TN];
#pragma unroll
            for (int i = 0; i < TM; i++) a[i] = As[kk][tr + i];
#pragma unroll
            for (int j = 0; j < TN; j++) b[j] = Bs[kk][tc + j];
#pragma unroll
            for (int i = 0; i < TM; i++)
#pragma unroll
                for (int j = 0; j < TN; j++) acc[i][j] += a[i] * b[j];
        }
        __syncthreads();
    }

#pragma unroll
    for (int i = 0; i < TM; i++)
#pragma unroll
        for (int j = 0; j < TN; j++) {
            int gm = m0 + tr + i, gn = n0 + tc + j;
            float val = acc[i][j];
            if (SUBI && gm == gn) val -= 1.0f;
            C[(size_t)gm * ldc + gn] = val;
        }
}

// ---------------------------------------------------------------------------
// Fused step kernel: S = act_r @ G, then AdamW update of (u, m, v) and
// act_w = relu(u_new - SHRINK). One element per output entry -> race-free.
// c1 = 1/(1-B1^t), c2 = 1/(1-B2^t).
// ---------------------------------------------------------------------------
__global__ __launch_bounds__(NTHR) void step_kernel(
    const float* __restrict__ act_r, float* __restrict__ act_w,
    float c1, float c2)
{
    __shared__ float As[BK][BM + 4];
    __shared__ float Bs[BK][BN + 4];

    const int tid = threadIdx.x;
    const int m0 = blockIdx.y * BM;
    const int n0 = blockIdx.x * BN;
    const int tr = (tid >> 4) * TM;
    const int tc = (tid & 15) * TN;

    float acc[TM][TN];
#pragma unroll
    for (int i = 0; i < TM; i++)
#pragma unroll
        for (int j = 0; j < TN; j++) acc[i][j] = 0.0f;

    for (int k0 = 0; k0 < NF; k0 += BK) {
#pragma unroll
        for (int t = 0; t < (BM * BK) / NTHR; t++) {
            int idx = tid + t * NTHR;
            int r = idx >> 4, c = idx & 15;
            As[c][r] = act_r[(size_t)(m0 + r) * NF + (k0 + c)];
        }
#pragma unroll
        for (int t = 0; t < (BN * BK) / NTHR; t++) {
            int idx = tid + t * NTHR;
            int n = idx & (BN - 1), kk = idx >> 7;
            Bs[kk][n] = g_G[(size_t)(k0 + kk) * NF + (n0 + n)];
        }
        __syncthreads();

#pragma unroll
        for (int kk = 0; kk < BK; kk++) {
            float a[TM], b[TN];
#pragma unroll
            for (int i = 0; i < TM; i++) a[i] = As[kk][tr + i];
#pragma unroll
            for (int j = 0; j < TN; j++) b[j] = Bs[kk][tc + j];
#pragma unroll
            for (int i = 0; i < TM; i++)
#pragma unroll
                for (int j = 0; j < TN; j++) acc[i][j] += a[i] * b[j];
        }
        __syncthreads();
    }

    // AdamW epilogue
#pragma unroll
    for (int i = 0; i < TM; i++)
#pragma unroll
        for (int j = 0; j < TN; j++) {
            size_t idx = (size_t)(m0 + tr + i) * NF + (n0 + tc + j);
            float s  = acc[i][j];
            float uo = g_u[idx];
            float g  = uo - g_excite[idx] + s;      // g = u - excite + act@G
            float mn = B1 * g_m[idx] + (1.0f - B1) * g;
            float vn = B2 * g_v[idx] + (1.0f - B2) * g * g;
            float un = uo * (1.0f - LR * WD);
            un -= LR * (mn * c1) / (sqrtf(vn * c2) + EPS);
            g_u[idx] = un;
            g_m[idx] = mn;
            g_v[idx] = vn;
            act_w[idx] = fmaxf(un - SHRINK, 0.0f);
        }
}

__global__ void init_kernel()
{
    size_t i = (size_t)blockIdx.x * blockDim.x + threadIdx.x;
    if (i < (size_t)NB * NF) {
        g_u[i] = 0.0f;
        g_m[i] = 0.0f;
        g_v[i] = 0.0f;
        g_acta[i] = 0.0f;
    }
}

extern "C" void kernel_launch(void* const* d_in, const int* in_sizes, int n_in,
                              void* d_out, int out_size)
{
    const float* images  = (const float*)d_in[0];
    const float* filters = (const float*)d_in[1];
    if (in_sizes[0] == NP * NF) {  // defensive: filters listed first
        filters = (const float*)d_in[0];
        images  = (const float*)d_in[1];
    }

    float *u, *excite, *G, *acta, *actb;
    cudaGetSymbolAddress((void**)&u, g_u);
    cudaGetSymbolAddress((void**)&excite, g_excite);
    cudaGetSymbolAddress((void**)&G, g_G);
    cudaGetSymbolAddress((void**)&acta, g_acta);
    cudaGetSymbolAddress((void**)&actb, g_actb);

    float* out = (float*)d_out;

    // Zero state (u, m, v, act) — must happen every call (graph replays).
    {
        int n = NB * NF;
        init_kernel<<<(n + 255) / 256, 256>>>();
    }

    // G = Phi^T Phi - I   (M=N=NF, K=NP; A accessed transposed)
    gemm_kernel<true, false, true><<<dim3(NF / BN, NF / BM), NTHR>>>(
        filters, filters, G, NF, NF, NP, NF, NF, NF);

    // excite = X @ Phi    (M=NB, N=NF, K=NP)
    gemm_kernel<false, false, false><<<dim3(NF / BN, NB / BM), NTHR>>>(
        images, filters, excite, NB, NF, NP, NP, NF, NF);

    // 50 AdamW steps, ping-pong act buffers
    float* bufs[2] = {acta, actb};
    double b1t = 1.0, b2t = 1.0;
    for (int t = 1; t <= STEPS; t++) {
        b1t *= (double)B1;
        b2t *= (double)B2;
        float c1 = (float)(1.0 / (1.0 - b1t));
        float c2 = (float)(1.0 / (1.0 - b2t));
        const float* rd = bufs[(t + 1) & 1];  // t=1 reads bufs[0] (zeros)
        float* wr = bufs[t & 1];
        step_kernel<<<dim3(NF / BN, NB / BM), NTHR>>>(rd, wr, c1, c2);
    }
    float* act_final = bufs[STEPS & 1];  // STEPS=50 -> bufs[0]

    // recon = act @ Phi^T  (M=NB, N=NP, K=NF; B accessed transposed)
    gemm_kernel<false, true, false><<<dim3(NP / BN, NB / BM), NTHR>>>(
        act_final, filters, out, NB, NP, NF, NF, NF, NP);

    // acts output after recon
    cudaMemcpyAsync(out + (size_t)NB * NP, act_final,
                    (size_t)NB * NF * sizeof(float),
                    cudaMemcpyDeviceToDevice);
}

// round 3
// speedup vs baseline: 2.4791x; 2.4791x over previous
#include <cuda_runtime.h>
#include <cuda_bf16.h>
#include <stdint.h>
#include <math.h>

#define NB 4096
#define NP 4096
#define NF 1024
#define SHRINK 0.25f
#define LR 0.1f
#define EPS 1e-8f
#define WD 1e-2f
#define STEPS 50

// tcgen05 only exists in the arch-accelerated (sm_103a / sm_100a) compilation
// pass. The harness also emits a plain compute_103 PTX target; give that pass
// an empty kernel body so ptxas never sees tcgen05. The runtime uses the
// sm_103a cubin from the fatbin.
#if defined(__CUDA_ARCH_FEAT_SM103_ALL) || defined(__CUDA_ARCH_FEAT_SM100_ALL) || \
    defined(__CUDA_ARCH_FEAT_SM101_ALL) || defined(__CUDA_ARCH_FEAT_SM120_ALL)
#define TC_OK 1
#else
#define TC_OK 0
#endif

// ---------------- persistent device state (no allocation allowed) ----------
__device__ float g_u[(size_t)NB * NF];
__device__ float g_m[(size_t)NB * NF];
__device__ float g_v[(size_t)NB * NF];
__device__ float g_excite[(size_t)NB * NF];
__device__ float g_act[(size_t)NB * NF];
__device__ __nv_bfloat16 g_acth[(size_t)NB * NF];
__device__ __nv_bfloat16 g_actl[(size_t)NB * NF];
__device__ __nv_bfloat16 g_imgh[(size_t)NB * NP];
__device__ __nv_bfloat16 g_imgl[(size_t)NB * NP];
__device__ __nv_bfloat16 g_phih[(size_t)NP * NF];   // Phi  [pixel][filter]
__device__ __nv_bfloat16 g_phil[(size_t)NP * NF];
__device__ __nv_bfloat16 g_phith[(size_t)NF * NP];  // Phi^T [filter][pixel]
__device__ __nv_bfloat16 g_phitl[(size_t)NF * NP];
__device__ __nv_bfloat16 g_Gh[(size_t)NF * NF];     // G = Phi^T Phi - I (symmetric)
__device__ __nv_bfloat16 g_Gl[(size_t)NF * NF];

// ---------------- PTX helpers ----------------------------------------------
__device__ __forceinline__ uint32_t smem_u32(const void* p) {
    uint32_t a;
    asm("{ .reg .u64 t; cvta.to.shared.u64 t, %1; cvt.u32.u64 %0, t; }"
        : "=r"(a) : "l"(p));
    return a;
}

__device__ __forceinline__ uint32_t elect_one() {
    uint32_t p;
    asm volatile("{\n\t.reg .pred p;\n\telect.sync _|p, 0xFFFFFFFF;\n\t"
                 "selp.b32 %0, 1, 0, p;\n\t}" : "=r"(p));
    return p;
}

__device__ __forceinline__ void cp_async16(uint32_t dst, const void* src) {
    asm volatile("cp.async.cg.shared.global [%0], [%1], 16;\n"
                 :: "r"(dst), "l"(src));
}
__device__ __forceinline__ void cp_commit() {
    asm volatile("cp.async.commit_group;\n" ::: "memory");
}
__device__ __forceinline__ void cp_wait0() {
    asm volatile("cp.async.wait_group 0;\n" ::: "memory");
}

__device__ __forceinline__ uint64_t mkdesc(uint32_t addr) {
    // SW128, Blackwell version=1, SBO=64 (1024B atom stride), LBO=1
    return ((uint64_t)2 << 61) | ((uint64_t)1 << 46) | ((uint64_t)64 << 32) |
           ((uint64_t)1 << 16) | ((uint64_t)(addr >> 4) & 0x3FFF);
}

// D = A @ B^T, bf16 in / fp32 acc, M=128, N=128, K=16 per call. SS mode, cg1.
__device__ __forceinline__ void mma_bf16_ss(uint32_t d_tmem, uint64_t a_desc,
                                            uint64_t b_desc, uint32_t idesc,
                                            bool acc) {
    uint32_t en = acc ? 1u : 0u;
    asm volatile(
        "{\n\t.reg .pred p;\n\tsetp.ne.u32 p, %5, 0;\n\t"
        "tcgen05.mma.cta_group::1.kind::f16 [%0], %1, %2, %3, {%4,%4,%4,%4}, p;\n\t}"
        :: "r"(d_tmem), "l"(a_desc), "l"(b_desc), "r"(idesc), "r"(0u), "r"(en)
        : "memory");
}

__device__ __forceinline__ void mbar_init(uint32_t a, uint32_t cnt) {
    asm volatile("mbarrier.init.shared.b64 [%0], %1;" :: "r"(a), "r"(cnt) : "memory");
}
__device__ __forceinline__ void mbar_wait(uint32_t a, uint32_t phase) {
    asm volatile(
        "{\n\t.reg .pred P;\n\tLW%=:\n\t"
        "mbarrier.try_wait.parity.shared.b64 P, [%0], %1;\n\t"
        "@!P bra LW%=;\n\t}" :: "r"(a), "r"(phase) : "memory");
}
__device__ __forceinline__ void tc_commit(uint32_t mbar) {
    asm volatile(
        "tcgen05.commit.cta_group::1.mbarrier::arrive::one.shared::cluster.b64 [%0];"
        :: "r"(mbar) : "memory");
}

__device__ __forceinline__ void ldtm32(uint32_t (&r)[32], uint32_t a) {
    asm volatile(
        "tcgen05.ld.sync.aligned.32x32b.x32.b32 "
        "{%0,%1,%2,%3,%4,%5,%6,%7,%8,%9,%10,%11,%12,%13,%14,%15,"
        "%16,%17,%18,%19,%20,%21,%22,%23,%24,%25,%26,%27,%28,%29,%30,%31}, [%32];"
        : "=r"(r[0]), "=r"(r[1]), "=r"(r[2]), "=r"(r[3]), "=r"(r[4]), "=r"(r[5]),
          "=r"(r[6]), "=r"(r[7]), "=r"(r[8]), "=r"(r[9]), "=r"(r[10]), "=r"(r[11]),
          "=r"(r[12]), "=r"(r[13]), "=r"(r[14]), "=r"(r[15]), "=r"(r[16]),
          "=r"(r[17]), "=r"(r[18]), "=r"(r[19]), "=r"(r[20]), "=r"(r[21]),
          "=r"(r[22]), "=r"(r[23]), "=r"(r[24]), "=r"(r[25]), "=r"(r[26]),
          "=r"(r[27]), "=r"(r[28]), "=r"(r[29]), "=r"(r[30]), "=r"(r[31])
        : "r"(a));
}

// idesc: F32 acc, BF16 a/b, N=128, M=128
#define IDESC 0x8200490u

// smem layout (dynamic): [0..4) tmem ptr, [8..16) mbar, [1024..) 2 stages x 4 tiles x 16KB
#define SM_BUF 1024
#define TILE_B 16384
#define STAGE_B (4 * TILE_B)
#define SMEM_SZ (SM_BUF + 2 * STAGE_B)

// Load one 128-row x 64-col bf16 tile (128B/row), SW128 swizzled, via cp.async.
__device__ __forceinline__ void load_tile(uint32_t dst, const __nv_bfloat16* src,
                                          int row0, int ld, int k0, int tid) {
    const char* base = (const char*)(src + (size_t)row0 * ld + k0);
    const size_t ldb = (size_t)ld * 2;
#pragma unroll
    for (int i = 0; i < 8; i++) {
        int cg = tid + i * 128;            // 0..1023
        int r = cg >> 3, c = cg & 7;
        uint32_t off = (uint32_t)(r * 128 + c * 16);
        uint32_t sw = off ^ ((off >> 3) & 0x70);
        cp_async16(dst + sw, base + (size_t)r * ldb + c * 16);
    }
}

struct GP {
    const __nv_bfloat16 *Ah, *Al, *Bh, *Bl;
    int ldA, ldB, kIters;
    float* outF; int ldc;         // EPI 0
    float c1, c2; int writeAct;   // EPI 2
};

// EPI: 0 = plain fp32 store, 1 = G (-I, bf16 split out), 2 = AdamW step
template <int EPI>
__global__ __launch_bounds__(128) void mma_gemm(GP P) {
#if TC_OK
    extern __shared__ char smem[];
    const uint32_t sb = smem_u32(smem);
    const int tid = threadIdx.x;
    const int wid = tid >> 5;
    const int m0 = blockIdx.y * 128, n0 = blockIdx.x * 128;

    if (wid == 0)
        asm volatile("tcgen05.alloc.cta_group::1.sync.aligned.shared::cta.b32 [%0], %1;"
                     :: "r"(sb + 0), "r"(128u) : "memory");
    if (tid == 0) mbar_init(sb + 8, 1);
    __syncthreads();
    uint32_t tbase;
    asm volatile("ld.shared.b32 %0, [%1];" : "=r"(tbase) : "r"(sb + 0));

    // prologue: stage 0 loads for k=0
    {
        uint32_t s0 = sb + SM_BUF;
        load_tile(s0 + 0 * TILE_B, P.Ah, m0, P.ldA, 0, tid);
        load_tile(s0 + 1 * TILE_B, P.Al, m0, P.ldA, 0, tid);
        load_tile(s0 + 2 * TILE_B, P.Bh, n0, P.ldB, 0, tid);
        load_tile(s0 + 3 * TILE_B, P.Bl, n0, P.ldB, 0, tid);
        cp_commit();
    }

    for (int k = 0; k < P.kIters; k++) {
        cp_wait0();
        __syncthreads();
        asm volatile("fence.proxy.async.shared::cta;" ::: "memory");

        const int cur = k & 1, nxt = cur ^ 1;
        if (k + 1 < P.kIters) {
            uint32_t sn = sb + SM_BUF + nxt * STAGE_B;
            int k0 = (k + 1) * 64;
            load_tile(sn + 0 * TILE_B, P.Ah, m0, P.ldA, k0, tid);
            load_tile(sn + 1 * TILE_B, P.Al, m0, P.ldA, k0, tid);
            load_tile(sn + 2 * TILE_B, P.Bh, n0, P.ldB, k0, tid);
            load_tile(sn + 3 * TILE_B, P.Bl, n0, P.ldB, k0, tid);
            cp_commit();
        }

        if (wid == 0) {
            if (elect_one()) {
                uint32_t sc = sb + SM_BUF + cur * STAGE_B;
                uint64_t ah = mkdesc(sc + 0 * TILE_B);
                uint64_t al = mkdesc(sc + 1 * TILE_B);
                uint64_t bh = mkdesc(sc + 2 * TILE_B);
                uint64_t bl = mkdesc(sc + 3 * TILE_B);
                bool first = (k == 0);
#pragma unroll
                for (int ks = 0; ks < 4; ks++)
                    mma_bf16_ss(tbase, ah + ks * 2, bh + ks * 2, IDESC,
                                !(first && ks == 0));
#pragma unroll
                for (int ks = 0; ks < 4; ks++)
                    mma_bf16_ss(tbase, ah + ks * 2, bl + ks * 2, IDESC, true);
#pragma unroll
                for (int ks = 0; ks < 4; ks++)
                    mma_bf16_ss(tbase, al + ks * 2, bh + ks * 2, IDESC, true);
                tc_commit(sb + 8);
            }
        }
        mbar_wait(sb + 8, k & 1);
    }

    asm volatile("tcgen05.fence::after_thread_sync;" ::: "memory");

    const int row = m0 + tid;   // thread tid owns M-row tid (warp = TMEM subpartition)
#pragma unroll
    for (int q = 0; q < 4; q++) {
        uint32_t d[32];
        ldtm32(d, tbase + q * 32);
        asm volatile("tcgen05.wait::ld.sync.aligned;" ::: "memory");
        const int cbase = n0 + q * 32;

        if constexpr (EPI == 0) {
            float4* o = (float4*)(P.outF + (size_t)row * P.ldc + cbase);
#pragma unroll
            for (int jj = 0; jj < 8; jj++) {
                float4 v;
                v.x = __uint_as_float(d[jj * 4 + 0]);
                v.y = __uint_as_float(d[jj * 4 + 1]);
                v.z = __uint_as_float(d[jj * 4 + 2]);
                v.w = __uint_as_float(d[jj * 4 + 3]);
                o[jj] = v;
            }
        } else if constexpr (EPI == 1) {
#pragma unroll
            for (int j = 0; j < 32; j++) {
                float val = __uint_as_float(d[j]);
                if (row == cbase + j) val -= 1.0f;
                __nv_bfloat16 h = __float2bfloat16(val);
                __nv_bfloat16 l = __float2bfloat16(val - __bfloat162float(h));
                size_t idx = (size_t)row * NF + cbase + j;
                g_Gh[idx] = h;
                g_Gl[idx] = l;
            }
        } else {
            const size_t base = (size_t)row * NF + cbase;
#pragma unroll
            for (int jj = 0; jj < 8; jj++) {
                float4 uo = *(const float4*)(g_u + base + jj * 4);
                float4 mo = *(const float4*)(g_m + base + jj * 4);
                float4 vo = *(const float4*)(g_v + base + jj * 4);
                float4 ex = *(const float4*)(g_excite + base + jj * 4);
                float ac[4];
                float uoa[4] = {uo.x, uo.y, uo.z, uo.w};
                float moa[4] = {mo.x, mo.y, mo.z, mo.w};
                float voa[4] = {vo.x, vo.y, vo.z, vo.w};
                float exa[4] = {ex.x, ex.y, ex.z, ex.w};
                float4 mn4, vn4, un4;
                float* mnp = &mn4.x; float* vnp = &vn4.x; float* unp = &un4.x;
#pragma unroll
                for (int c = 0; c < 4; c++) {
                    float s = __uint_as_float(d[jj * 4 + c]);
                    float g = uoa[c] - exa[c] + s;
                    float mn = 0.9f * moa[c] + 0.1f * g;
                    float vn = 0.999f * voa[c] + 0.001f * g * g;
                    float u2 = uoa[c] * (1.0f - LR * WD);
                    u2 -= LR * (mn * P.c1) / (sqrtf(vn * P.c2) + EPS);
                    mnp[c] = mn; vnp[c] = vn; unp[c] = u2;
                    ac[c] = fmaxf(u2 - SHRINK, 0.0f);
                }
                *(float4*)(g_u + base + jj * 4) = un4;
                *(float4*)(g_m + base + jj * 4) = mn4;
                *(float4*)(g_v + base + jj * 4) = vn4;
#pragma unroll
                for (int c = 0; c < 4; c++) {
                    __nv_bfloat16 h = __float2bfloat16(ac[c]);
                    __nv_bfloat16 l = __float2bfloat16(ac[c] - __bfloat162float(h));
                    g_acth[base + jj * 4 + c] = h;
                    g_actl[base + jj * 4 + c] = l;
                }
                if (P.writeAct) {
                    float4 a4; a4.x = ac[0]; a4.y = ac[1]; a4.z = ac[2]; a4.w = ac[3];
                    *(float4*)(g_act + base + jj * 4) = a4;
                }
            }
        }
    }

    asm volatile("tcgen05.fence::before_thread_sync;" ::: "memory");
    __syncthreads();
    if (wid == 0) {
        asm volatile("tcgen05.dealloc.cta_group::1.sync.aligned.b32 %0, %1;"
                     :: "r"(tbase), "r"(128u));
    }
#else
    // Fallback for the non-accelerated PTX target: never executed at runtime
    // (the fatbin's sm_103a cubin is always selected on GB300).
    (void)P;
#endif
}

// ---------------- init / convert kernels ------------------------------------
__global__ void k_init() {
    size_t i = (size_t)blockIdx.x * blockDim.x + threadIdx.x;
    if (i < (size_t)NB * NF) {
        g_u[i] = 0.0f; g_m[i] = 0.0f; g_v[i] = 0.0f;
        g_acth[i] = __float2bfloat16(0.0f);
        g_actl[i] = __float2bfloat16(0.0f);
    }
}

__global__ void k_conv_img(const float* __restrict__ img) {
    size_t i = (size_t)blockIdx.x * blockDim.x + threadIdx.x;
    if (i < (size_t)NB * NP) {
        float x = img[i];
        __nv_bfloat16 h = __float2bfloat16(x);
        g_imgh[i] = h;
        g_imgl[i] = __float2bfloat16(x - __bfloat162float(h));
    }
}

__global__ void k_conv_phi(const float* __restrict__ f) {
    size_t i = (size_t)blockIdx.x * blockDim.x + threadIdx.x;
    if (i < (size_t)NP * NF) {
        int p = (int)(i / NF), c = (int)(i % NF);
        float x = f[i];
        __nv_bfloat16 h = __float2bfloat16(x);
        __nv_bfloat16 l = __float2bfloat16(x - __bfloat162float(h));
        g_phih[i] = h; g_phil[i] = l;
        g_phith[(size_t)c * NP + p] = h;
        g_phitl[(size_t)c * NP + p] = l;
    }
}

// ---------------- launcher ---------------------------------------------------
extern "C" void kernel_launch(void* const* d_in, const int* in_sizes, int n_in,
                              void* d_out, int out_size) {
    const float* images  = (const float*)d_in[0];
    const float* filters = (const float*)d_in[1];
    if (in_sizes[0] == NP * NF && in_sizes[1] == NB * NP) {
        filters = (const float*)d_in[0];
        images  = (const float*)d_in[1];
    }
    float* out = (float*)d_out;

    cudaFuncSetAttribute(mma_gemm<0>, cudaFuncAttributeMaxDynamicSharedMemorySize, SMEM_SZ);
    cudaFuncSetAttribute(mma_gemm<1>, cudaFuncAttributeMaxDynamicSharedMemorySize, SMEM_SZ);
    cudaFuncSetAttribute(mma_gemm<2>, cudaFuncAttributeMaxDynamicSharedMemorySize, SMEM_SZ);

    const __nv_bfloat16 *imgh, *imgl, *phih, *phil, *phith, *phitl, *Gh, *Gl, *acth, *actl;
    float* act;
    cudaGetSymbolAddress((void**)&imgh, g_imgh);
    cudaGetSymbolAddress((void**)&imgl, g_imgl);
    cudaGetSymbolAddress((void**)&phih, g_phih);
    cudaGetSymbolAddress((void**)&phil, g_phil);
    cudaGetSymbolAddress((void**)&phith, g_phith);
    cudaGetSymbolAddress((void**)&phitl, g_phitl);
    cudaGetSymbolAddress((void**)&Gh, g_Gh);
    cudaGetSymbolAddress((void**)&Gl, g_Gl);
    cudaGetSymbolAddress((void**)&acth, g_acth);
    cudaGetSymbolAddress((void**)&actl, g_actl);
    cudaGetSymbolAddress((void**)&act, g_act);
    float* excite;
    cudaGetSymbolAddress((void**)&excite, g_excite);

    {
        size_t n = (size_t)NB * NF;
        k_init<<<(unsigned)((n + 255) / 256), 256>>>();
    }
    {
        size_t n = (size_t)NB * NP;
        k_conv_img<<<(unsigned)((n + 255) / 256), 256>>>(images);
    }
    {
        size_t n = (size_t)NP * NF;
        k_conv_phi<<<(unsigned)((n + 255) / 256), 256>>>(filters);
    }

    GP p{};

    // G = Phi^T @ (Phi^T)^T - I   (M=N=NF, K=NP), output bf16 split (symmetric)
    p.Ah = phith; p.Al = phitl; p.Bh = phith; p.Bl = phitl;
    p.ldA = NP; p.ldB = NP; p.kIters = NP / 64;
    mma_gemm<1><<<dim3(NF / 128, NF / 128), 128, SMEM_SZ>>>(p);

    // excite = images @ Phi  (B rows = Phi^T rows), fp32 out
    p.Ah = imgh; p.Al = imgl; p.Bh = phith; p.Bl = phitl;
    p.ldA = NP; p.ldB = NP; p.kIters = NP / 64;
    p.outF = excite; p.ldc = NF;
    mma_gemm<0><<<dim3(NF / 128, NB / 128), 128, SMEM_SZ>>>(p);

    // 50 AdamW steps: S = act @ G (G symmetric -> B rows = G rows)
    double b1t = 1.0, b2t = 1.0;
    for (int t = 1; t <= STEPS; t++) {
        b1t *= 0.9; b2t *= 0.999;
        GP sp{};
        sp.Ah = acth; sp.Al = actl; sp.Bh = Gh; sp.Bl = Gl;
        sp.ldA = NF; sp.ldB = NF; sp.kIters = NF / 64;
        sp.c1 = (float)(1.0 / (1.0 - b1t));
        sp.c2 = (float)(1.0 / (1.0 - b2t));
        sp.writeAct = (t == STEPS) ? 1 : 0;
        mma_gemm<2><<<dim3(NF / 128, NB / 128), 128, SMEM_SZ>>>(sp);
    }

    // recon = act @ Phi^T  (B rows = Phi rows), fp32 -> d_out
    GP rp{};
    rp.Ah = acth; rp.Al = actl; rp.Bh = phih; rp.Bl = phil;
    rp.ldA = NF; rp.ldB = NF; rp.kIters = NF / 64;
    rp.outF = out; rp.ldc = NP;
    mma_gemm<0><<<dim3(NP / 128, NB / 128), 128, SMEM_SZ>>>(rp);

    // acts output after recon
    cudaMemcpyAsync(out + (size_t)NB * NP, act,
                    (size_t)NB * NF * sizeof(float), cudaMemcpyDeviceToDevice);
}